// round 1
// baseline (speedup 1.0000x reference)
#include <cuda_runtime.h>

#define B 8
#define M 8192
#define N 8192
#define SPLITS 64
#define ROWS (M / SPLITS)            // 128 rows per split
#define TPB 128
#define COLS_PER_BLOCK (TPB * 4)     // 512 columns per block (float4 per thread)
#define NBLK (N / COLS_PER_BLOCK)    // 16 column blocks

// Split-K partial sums: [SPLITS][B][N] floats = 16 MB device scratch.
__device__ float g_part[(size_t)SPLITS * B * N];

__global__ void __launch_bounds__(TPB)
snn_gemv_split(const float* __restrict__ pre,   // [B][M]
               const float* __restrict__ W)     // [M][N] row-major
{
    __shared__ float pre_s[ROWS][B];

    const int nb  = blockIdx.x;   // which 512-column tile
    const int s   = blockIdx.y;   // which M split
    const int tid = threadIdx.x;
    const int m0  = s * ROWS;

    // Stage pre-spike slice [ROWS][B] into smem (coalesced global reads).
    #pragma unroll
    for (int b = 0; b < B; b++)
        pre_s[tid][b] = pre[b * M + m0 + tid];
    __syncthreads();

    const int n0 = nb * COLS_PER_BLOCK + tid * 4;
    const float4* Wp = reinterpret_cast<const float4*>(W + (size_t)m0 * N + n0);

    float4 acc[B];
    #pragma unroll
    for (int b = 0; b < B; b++)
        acc[b] = make_float4(0.f, 0.f, 0.f, 0.f);

    #pragma unroll 4
    for (int m = 0; m < ROWS; m++) {
        float4 w = Wp[(size_t)m * (N / 4)];   // 512 B contiguous per warp per row

        float p[B];
        *reinterpret_cast<float4*>(&p[0]) =
            *reinterpret_cast<const float4*>(&pre_s[m][0]);   // broadcast LDS.128
        *reinterpret_cast<float4*>(&p[4]) =
            *reinterpret_cast<const float4*>(&pre_s[m][4]);

        #pragma unroll
        for (int b = 0; b < B; b++) {
            acc[b].x += p[b] * w.x;
            acc[b].y += p[b] * w.y;
            acc[b].z += p[b] * w.z;
            acc[b].w += p[b] * w.w;
        }
    }

    #pragma unroll
    for (int b = 0; b < B; b++) {
        *reinterpret_cast<float4*>(&g_part[((size_t)s * B + b) * N + n0]) = acc[b];
    }
}

__global__ void __launch_bounds__(TPB)
snn_reduce(const float* __restrict__ thr,       // [B][N]
           const float* __restrict__ cst,       // [B][N]
           float* __restrict__ out)             // [B][N]
{
    const int idx4 = blockIdx.x * blockDim.x + threadIdx.x;  // over B*N/4
    const int base = idx4 * 4;

    float4 sum = make_float4(0.f, 0.f, 0.f, 0.f);
    #pragma unroll 8
    for (int s = 0; s < SPLITS; s++) {
        float4 v = *reinterpret_cast<const float4*>(&g_part[(size_t)s * B * N + base]);
        sum.x += v.x; sum.y += v.y; sum.z += v.z; sum.w += v.w;
    }

    float4 t = *reinterpret_cast<const float4*>(&thr[base]);
    float4 c = *reinterpret_cast<const float4*>(&cst[base]);

    float4 o;
    o.x = fminf(fmaxf(sum.x + c.x - t.x, 0.f), 0.9f);
    o.y = fminf(fmaxf(sum.y + c.y - t.y, 0.f), 0.9f);
    o.z = fminf(fmaxf(sum.z + c.z - t.z, 0.f), 0.9f);
    o.w = fminf(fmaxf(sum.w + c.w - t.w, 0.f), 0.9f);

    *reinterpret_cast<float4*>(&out[base]) = o;
}

extern "C" void kernel_launch(void* const* d_in, const int* in_sizes, int n_in,
                              void* d_out, int out_size)
{
    const float* pre = (const float*)d_in[0];   // pre_spikes [8,1,8192]
    const float* W   = (const float*)d_in[1];   // W [8192,8192]
    const float* thr = (const float*)d_in[2];   // thr [8,1,8192]
    const float* cst = (const float*)d_in[3];   // const_inp [8,1,8192]
    float* out = (float*)d_out;                 // [8,1,8192]

    dim3 grid(NBLK, SPLITS);
    snn_gemv_split<<<grid, TPB>>>(pre, W);

    const int total4 = (B * N) / 4;             // 16384
    snn_reduce<<<total4 / TPB, TPB>>>(thr, cst, out);
}